// round 9
// baseline (speedup 1.0000x reference)
#include <cuda_runtime.h>
#include <cuda_fp16.h>
#include <math.h>
#include <stdint.h>

// ---------------- problem constants ----------------
#define Bv 16
#define Nv 128
#define Dv 256
#define Hv 8
#define BM (Bv*Nv)                               // 2048 (b,m) pairs
#define EDGE_ELEMS ((size_t)Bv*Nv*Nv*Dv)         // 67108864
#define INV_SQRT_DK 0.17677669529663688f
#define NCHUNK 4
#define CHUNK_BM (BM/NCHUNK)                     // 512

// ---------------- device scratch (no runtime alloc) ----------------
__device__ float g_WqT[Dv*Dv];
__device__ float g_WvT[Dv*Dv];
__device__ float g_qW[(size_t)BM*Hv*Dv];          // [(bm*8+h)*256+j], pre-scaled
__device__ __half2 g_vprojP[(size_t)Bv*64*Dv];    // n-paired half2: [b*64+n2][d]
__device__ __half2 g_WnTp[128*Dv];                // j-paired half2: [j2][d]
__device__ float g_attn[(size_t)BM*Nv*Hv];        // [bm][n][h]
// B fragments as tile-pairs: [(kt*16 + tp)*32 + lane] = (t0.b0,t0.b1,t1.b0,t1.b1)
__device__ uint4 g_fragK4[16*16*32];
__device__ uint4 g_fragE4[16*16*32];

// fast exact-identity mish: x*tanh(log1p(e^x)) == x*(u^2-1)/(u^2+1), u=1+e^x
__device__ __forceinline__ float mishf(float x) {
    if (x > 20.0f) return x;
    float t  = __expf(x);
    float u  = 1.0f + t;
    float u2 = u * u;
    return x * __fdividef(u2 - 1.0f, u2 + 1.0f);
}
__device__ __forceinline__ unsigned h2u(__half a, __half b) {
    return (unsigned)__half_as_ushort(a) | ((unsigned)__half_as_ushort(b) << 16);
}
__device__ __forceinline__ unsigned h2pack(__half2 h) {
    return *reinterpret_cast<unsigned*>(&h);
}
__device__ __forceinline__ uint32_t smem_u32(const void* p) {
    uint32_t a;
    asm("{ .reg .u64 t; cvta.to.shared.u64 t, %1; cvt.u32.u64 %0, t; }" : "=r"(a) : "l"(p));
    return a;
}
__device__ __forceinline__ void mma16816(float* d, const unsigned* a,
                                         unsigned b0, unsigned b1) {
    asm volatile(
        "mma.sync.aligned.m16n8k16.row.col.f32.f16.f16.f32 "
        "{%0,%1,%2,%3},{%4,%5,%6,%7},{%8,%9},{%0,%1,%2,%3};"
        : "+f"(d[0]), "+f"(d[1]), "+f"(d[2]), "+f"(d[3])
        : "r"(a[0]), "r"(a[1]), "r"(a[2]), "r"(a[3]), "r"(b0), "r"(b1));
}
__device__ __forceinline__ void ldsm_x4(unsigned* a, uint32_t addr) {
    asm volatile("ldmatrix.sync.aligned.m8n8.x4.shared.b16 {%0,%1,%2,%3}, [%4];"
        : "=r"(a[0]), "=r"(a[1]), "=r"(a[2]), "=r"(a[3]) : "r"(addr));
}

// ---------------- K1: weight prep (320 blocks x 256) ----------------
__global__ void wprep_kernel(const float* __restrict__ Wq, const float* __restrict__ Wv,
                             const float* __restrict__ Wn,
                             const float* __restrict__ Wk, const float* __restrict__ We) {
    int blk = blockIdx.x, tid = threadIdx.x;
    if (blk < 128) {
        int which = blk >> 6, t2 = blk & 63;
        const float* src = (which == 0) ? Wq : Wv;
        float* dst = (which == 0) ? g_WqT : g_WvT;
        __shared__ float t[32][33];
        int x0 = (t2 & 7) * 32, y0 = (t2 >> 3) * 32;
        int tx = tid & 31, ty = tid >> 5;
        #pragma unroll
        for (int i = 0; i < 32; i += 8) t[ty + i][tx] = src[(y0 + ty + i) * Dv + x0 + tx];
        __syncthreads();
        #pragma unroll
        for (int i = 0; i < 32; i += 8) dst[(x0 + ty + i) * Dv + y0 + tx] = t[tx][ty + i];
    } else if (blk < 256) {
        int e = (blk - 128) * 256 + tid;          // 0..32767
        int j2 = e >> 8, d = e & 255;
        g_WnTp[e] = __floats2half2_rn(Wn[d * Dv + 2 * j2], Wn[d * Dv + 2 * j2 + 1]);
    } else {
        int g = (blk - 256) * 256 + tid;          // 0..16383
        int mat = g >> 13;
        int r = g & 8191;
        int kt = r >> 9, tp = (r >> 5) & 15, lane = r & 31;
        const float* W = mat ? We : Wk;
        int k0 = kt * 16 + (lane & 3) * 2;
        int n0 = (2 * tp) * 8 + (lane >> 2);
        int n1 = n0 + 8;
        uint4 f;
        f.x = h2u(__float2half_rn(W[n0 * Dv + k0]),     __float2half_rn(W[n0 * Dv + k0 + 1]));
        f.y = h2u(__float2half_rn(W[n0 * Dv + k0 + 8]), __float2half_rn(W[n0 * Dv + k0 + 9]));
        f.z = h2u(__float2half_rn(W[n1 * Dv + k0]),     __float2half_rn(W[n1 * Dv + k0 + 1]));
        f.w = h2u(__float2half_rn(W[n1 * Dv + k0 + 8]), __float2half_rn(W[n1 * Dv + k0 + 9]));
        if (mat) g_fragE4[r] = f;
        else     g_fragK4[r] = f;
    }
}

// ---------------- K2: batched q/v projections + qW fold (128 CTAs x 16 bm) ----------------
__global__ void __launch_bounds__(256) prep2_kernel(
    const float* __restrict__ qn, const float* __restrict__ vn,
    const float* __restrict__ Wk,
    const float* __restrict__ bq, const float* __restrict__ bv)
{
    __shared__ float sIn[16 * 256];
    __shared__ float sQp[16 * 256];
    int tid = threadIdx.x;
    int bm0 = blockIdx.x * 16;

    for (int e = tid; e < 16 * 256; e += 256) sIn[e] = qn[(size_t)bm0 * 256 + e];
    __syncthreads();
    {
        float acc[16];
        float bqv = bq[tid];
        #pragma unroll
        for (int r = 0; r < 16; ++r) acc[r] = bqv;
        #pragma unroll 4
        for (int j = 0; j < 256; ++j) {
            float w = g_WqT[j * 256 + tid];
            #pragma unroll
            for (int r = 0; r < 16; ++r) acc[r] += sIn[r * 256 + j] * w;
        }
        #pragma unroll
        for (int r = 0; r < 16; ++r) sQp[r * 256 + tid] = acc[r];
    }
    __syncthreads();
    for (int e = tid; e < 16 * 256; e += 256) sIn[e] = vn[(size_t)bm0 * 256 + e];
    __syncthreads();
    {
        float acc[16];
        float bvv = bv[tid];
        #pragma unroll
        for (int r = 0; r < 16; ++r) acc[r] = bvv;
        #pragma unroll 4
        for (int j = 0; j < 256; ++j) {
            float w = g_WvT[j * 256 + tid];
            #pragma unroll
            for (int r = 0; r < 16; ++r) acc[r] += sIn[r * 256 + j] * w;
        }
        int b = bm0 >> 7, n2base = (bm0 & 127) >> 1;
        #pragma unroll
        for (int i = 0; i < 8; ++i)
            g_vprojP[((size_t)b * 64 + n2base + i) * 256 + tid] =
                __floats2half2_rn(acc[2 * i], acc[2 * i + 1]);
    }
    #pragma unroll 1
    for (int h = 0; h < 8; ++h) {
        float acc[16];
        #pragma unroll
        for (int r = 0; r < 16; ++r) acc[r] = 0.0f;
        #pragma unroll 4
        for (int dk = 0; dk < 32; ++dk) {
            float w = Wk[(h * 32 + dk) * 256 + tid];
            #pragma unroll
            for (int r = 0; r < 16; ++r) acc[r] += sQp[r * 256 + h * 32 + dk] * w;
        }
        #pragma unroll
        for (int r = 0; r < 16; ++r)
            g_qW[((size_t)(bm0 + r) * 8 + h) * 256 + tid] = acc[r] * INV_SQRT_DK;
    }
}

// ---------------- K3: attention via MMA — CHUNK_BM CTAs x 256, 2 CTAs/SM ----------------
#define PITCH 264
#define A_SA_OFF   0                              // 128*264*2 = 67584
#define A_QW_OFF   67584                          // 8*260*4 = 8320
#define A_AT_OFF   (A_QW_OFF + 8320)              // 4096
#define A_ND_OFF   (A_AT_OFF + 4096)              // 1024
#define A_SMEM_TOTAL (A_ND_OFF + 1024)            // 81024

__global__ void __launch_bounds__(256, 2) attn_kernel(
    const float* __restrict__ key_edge,
    const float* __restrict__ bn,
    float* __restrict__ out, int bmBase)
{
    extern __shared__ char sm[];
    __half* sA   = (__half*)(sm + A_SA_OFF);
    float* sQW   = (float*)(sm + A_QW_OFF);
    float* sAttn = (float*)(sm + A_AT_OFF);
    float* sNode = (float*)(sm + A_ND_OFF);

    const int tid = threadIdx.x, lane = tid & 31, warp = tid >> 5;
    const int bm = bmBase + blockIdx.x, b = bm >> 7;

    for (int i = tid; i < 8 * 256; i += 256)
        sQW[(i >> 8) * 260 + (i & 255)] = g_qW[(size_t)bm * 2048 + i];

    // ---- load KE (fp32 global) -> sA (fp16) ----
    const float* keb = key_edge + (size_t)bm * (Nv * Dv);
    {
        const int r4 = tid >> 6, c4 = (tid & 63) * 4;
        #pragma unroll 4
        for (int rr = 0; rr < 128; rr += 4) {
            int row = rr + r4;
            float4 v = *(const float4*)&keb[(size_t)row * 256 + c4];
            uint2 p;
            p.x = h2pack(__floats2half2_rn(v.x, v.y));
            p.y = h2pack(__floats2half2_rn(v.z, v.w));
            *(uint2*)&sA[row * PITCH + c4] = p;
        }
    }
    __syncthreads();

    // ---- scores via MMA, inline hi/lo qW fragments (warp = 16 rows) ----
    {
        const int rowsel = (lane & 7) + ((lane >> 3) & 1) * 8;
        const int colsel = (lane >> 4) * 8;
        uint32_t lmS = smem_u32(sA) + (uint32_t)(((warp * 16 + rowsel) * PITCH + colsel) * 2);
        const int hB  = lane >> 2;
        const int kq2 = (lane & 3) * 2;
        float sc[4] = {0.0f, 0.0f, 0.0f, 0.0f};
        #pragma unroll 1
        for (int kt = 0; kt < 16; ++kt) {
            unsigned a[4];
            ldsm_x4(a, lmS + kt * 32);
            float2 qa = *(float2*)&sQW[hB * 260 + kt * 16 + kq2];
            float2 qb = *(float2*)&sQW[hB * 260 + kt * 16 + kq2 + 8];
            __half2 ha = __floats2half2_rn(qa.x, qa.y);
            __half2 hb = __floats2half2_rn(qb.x, qb.y);
            float2 ra = __half22float2(ha), rb = __half22float2(hb);
            __half2 la = __floats2half2_rn(qa.x - ra.x, qa.y - ra.y);
            __half2 lb = __floats2half2_rn(qb.x - rb.x, qb.y - rb.y);
            mma16816(sc, a, h2pack(ha), h2pack(hb));   // hi
            mma16816(sc, a, h2pack(la), h2pack(lb));   // lo
        }
        int rD = warp * 16 + (lane >> 2);
        int hD = (lane & 3) * 2;
        sAttn[hD * 128 + rD]           = sc[0];
        sAttn[(hD + 1) * 128 + rD]     = sc[1];
        sAttn[hD * 128 + rD + 8]       = sc[2];
        sAttn[(hD + 1) * 128 + rD + 8] = sc[3];
    }
    __syncthreads();

    // ---- softmax (warp per head) ----
    {
        int h = warp;
        float s[4];
        #pragma unroll
        for (int i = 0; i < 4; ++i) s[i] = sAttn[h * 128 + lane + 32 * i];
        float mx = fmaxf(fmaxf(s[0], s[1]), fmaxf(s[2], s[3]));
        #pragma unroll
        for (int off = 16; off > 0; off >>= 1)
            mx = fmaxf(mx, __shfl_xor_sync(0xffffffffu, mx, off));
        float e[4], sum = 0.0f;
        #pragma unroll
        for (int i = 0; i < 4; ++i) { e[i] = __expf(s[i] - mx); sum += e[i]; }
        #pragma unroll
        for (int off = 16; off > 0; off >>= 1)
            sum += __shfl_xor_sync(0xffffffffu, sum, off);
        float inv = __fdividef(1.0f, sum);
        #pragma unroll
        for (int i = 0; i < 4; ++i) sAttn[h * 128 + lane + 32 * i] = e[i] * inv;
    }
    __syncthreads();

    // ---- write g_attn [bm][n][h] ----
    for (int e = tid; e < 1024; e += 256)
        g_attn[(size_t)bm * 1024 + e] = sAttn[(e & 7) * 128 + (e >> 3)];

    // ---- node path (half2 packed) ----
    {
        int h = tid >> 5;
        const __half2* vp = g_vprojP + (size_t)b * 64 * 256 + tid;
        const float* att = &sAttn[h * 128];
        float accN = 0.0f;
        #pragma unroll 4
        for (int n2 = 0; n2 < 64; ++n2) {
            float2 v = __half22float2(vp[n2 * 256]);
            accN += att[2 * n2] * v.x + att[2 * n2 + 1] * v.y;
        }
        sNode[tid] = accN;
        __syncthreads();
        float acc2 = bn[tid];
        #pragma unroll 4
        for (int j2 = 0; j2 < 128; ++j2) {
            float2 w = __half22float2(g_WnTp[j2 * 256 + tid]);
            acc2 += sNode[2 * j2] * w.x + sNode[2 * j2 + 1] * w.y;
        }
        out[EDGE_ELEMS + (size_t)bm * 256 + tid] = mishf(acc2);
    }
}

// ---------------- K4: edge GEMM kernel — 2*CHUNK_BM CTAs x 256, 3 CTAs/SM ----------------
#define SA_OFF   0                               // 64*264*2 = 33792
#define SA2_OFF  33792                           // 33792
#define SAT_OFF  67584                           // 64*8*4 = 2048
#define SBK_OFF  69632                           // 1024
#define SBE_OFF  70656                           // 1024
#define ESMEM_TOTAL 71680

__device__ __forceinline__ void gemm_pass_e(float acc[2][4][4], uint32_t lm0, uint32_t lm1,
                                            const uint4* __restrict__ frag, int tpBase, int lane) {
    #pragma unroll
    for (int mi = 0; mi < 2; ++mi)
        #pragma unroll
        for (int t = 0; t < 4; ++t)
            #pragma unroll
            for (int q = 0; q < 4; ++q) acc[mi][t][q] = 0.0f;

    const uint4* fp = frag + (size_t)tpBase * 32 + lane;
    uint4 bf0 = __ldg(fp), bf1 = __ldg(fp + 32);
    #pragma unroll 1
    for (int kt = 0; kt < 16; ++kt) {
        unsigned a0[4], a1[4];
        ldsm_x4(a0, lm0 + kt * 32);
        ldsm_x4(a1, lm1 + kt * 32);
        uint4 bn0, bn1;
        if (kt < 15) { bn0 = __ldg(fp + (kt + 1) * 512); bn1 = __ldg(fp + (kt + 1) * 512 + 32); }
        mma16816(acc[0][0], a0, bf0.x, bf0.y);
        mma16816(acc[1][0], a1, bf0.x, bf0.y);
        mma16816(acc[0][1], a0, bf0.z, bf0.w);
        mma16816(acc[1][1], a1, bf0.z, bf0.w);
        mma16816(acc[0][2], a0, bf1.x, bf1.y);
        mma16816(acc[1][2], a1, bf1.x, bf1.y);
        mma16816(acc[0][3], a0, bf1.z, bf1.w);
        mma16816(acc[1][3], a1, bf1.z, bf1.w);
        if (kt < 15) { bf0 = bn0; bf1 = bn1; }
    }
}

__global__ void __launch_bounds__(256, 3) edge_kernel(
    const float* __restrict__ key_edge,
    const float* __restrict__ bk, const float* __restrict__ be,
    float* __restrict__ out, int bmBase)
{
    extern __shared__ char sm[];
    __half* sA  = (__half*)(sm + SA_OFF);
    __half* sA2 = (__half*)(sm + SA2_OFF);
    float* sAt  = (float*)(sm + SAT_OFF);
    float* sBk  = (float*)(sm + SBK_OFF);
    float* sBe  = (float*)(sm + SBE_OFF);

    const int tid = threadIdx.x, lane = tid & 31, warp = tid >> 5;
    const int bm = bmBase + (blockIdx.x >> 1), half = blockIdx.x & 1;

    sBk[tid] = bk[tid];
    sBe[tid] = be[tid];
    for (int e = tid; e < 512; e += 256)
        sAt[e] = g_attn[(size_t)bm * 1024 + half * 512 + e];

    const float* keb = key_edge + ((size_t)bm * 128 + half * 64) * 256;
    {
        const int r4 = tid >> 6, c4 = (tid & 63) * 4;
        #pragma unroll 4
        for (int rr = 0; rr < 64; rr += 4) {
            int row = rr + r4;
            float4 v = *(const float4*)&keb[(size_t)row * 256 + c4];
            uint2 p;
            p.x = h2pack(__floats2half2_rn(v.x, v.y));
            p.y = h2pack(__floats2half2_rn(v.z, v.w));
            *(uint2*)&sA[row * PITCH + c4] = p;
        }
    }
    __syncthreads();

    const int wi = warp & 1;
    const int wj = warp >> 1;
    const int rA = lane >> 2;
    const int kq = (lane & 3) * 2;
    const int rowsel = (lane & 7) + ((lane >> 3) & 1) * 8;
    const int colsel = (lane >> 4) * 8;
    const uint32_t smbA  = smem_u32(sA);
    const uint32_t smbA2 = smem_u32(sA2);
    const uint32_t lmA0 = smbA + (uint32_t)(((wi * 32 + rowsel) * PITCH + colsel) * 2);
    const uint32_t lmA1 = lmA0 + 16 * PITCH * 2;
    const uint32_t lmB0 = smbA2 + (uint32_t)(((wi * 32 + rowsel) * PITCH + colsel) * 2);
    const uint32_t lmB1 = lmB0 + 16 * PITCH * 2;

    float acc[2][4][4];

    #pragma unroll 1
    for (int np = 0; np < 2; ++np) {
        gemm_pass_e(acc, lmA0, lmA1, g_fragK4, np * 8 + wj * 2, lane);
        #pragma unroll
        for (int mi = 0; mi < 2; ++mi) {
            #pragma unroll
            for (int t = 0; t < 4; ++t) {
                int r0 = wi * 32 + mi * 16 + rA;
                int c  = np * 128 + wj * 32 + t * 8 + kq;
                float b0 = sBk[c], b1 = sBk[c + 1];
                int hh = c >> 5;
                float a0 = sAt[r0 * 8 + hh], a8 = sAt[(r0 + 8) * 8 + hh];
                *(unsigned*)&sA2[r0 * PITCH + c] =
                    h2pack(__floats2half2_rn((acc[mi][t][0] + b0) * a0, (acc[mi][t][1] + b1) * a0));
                *(unsigned*)&sA2[(r0 + 8) * PITCH + c] =
                    h2pack(__floats2half2_rn((acc[mi][t][2] + b0) * a8, (acc[mi][t][3] + b1) * a8));
            }
        }
    }
    __syncthreads();

    #pragma unroll 1
    for (int np = 0; np < 2; ++np) {
        gemm_pass_e(acc, lmB0, lmB1, g_fragE4, np * 8 + wj * 2, lane);
        #pragma unroll
        for (int mi = 0; mi < 2; ++mi) {
            #pragma unroll
            for (int t = 0; t < 4; ++t) {
                int r0 = wi * 32 + mi * 16 + rA;
                int c  = np * 128 + wj * 32 + t * 8 + kq;
                float b0 = sBe[c], b1 = sBe[c + 1];
                size_t gr = ((size_t)bm * 128 + half * 64 + r0) * 256 + c;
                float2 o0, o1;
                o0.x = mishf(acc[mi][t][0] + b0);
                o0.y = mishf(acc[mi][t][1] + b1);
                o1.x = mishf(acc[mi][t][2] + b0);
                o1.y = mishf(acc[mi][t][3] + b1);
                *(float2*)&out[gr]            = o0;
                *(float2*)&out[gr + 8 * 256]  = o1;
            }
        }
    }
}

// ---------------------------------------------------------------------------
extern "C" void kernel_launch(void* const* d_in, const int* in_sizes, int n_in,
                              void* d_out, int out_size) {
    (void)in_sizes; (void)n_in; (void)out_size;
    const float* qn = (const float*)d_in[0];
    const float* vn = (const float*)d_in[1];
    const float* ke = (const float*)d_in[2];
    const float* Wq = (const float*)d_in[4];
    const float* bq = (const float*)d_in[5];
    const float* Wk = (const float*)d_in[6];
    const float* bk = (const float*)d_in[7];
    const float* Wv = (const float*)d_in[8];
    const float* bv = (const float*)d_in[9];
    const float* We = (const float*)d_in[10];
    const float* be = (const float*)d_in[11];
    const float* Wn = (const float*)d_in[12];
    const float* bn = (const float*)d_in[13];
    float* out = (float*)d_out;

    // one-time resources (creation only; identical launched work on every call)
    static cudaStream_t s2 = []() {
        cudaStream_t s; cudaStreamCreateWithFlags(&s, cudaStreamNonBlocking); return s;
    }();
    static cudaEvent_t evA[NCHUNK] = {};
    static cudaEvent_t evJoin = []() {
        for (int i = 0; i < NCHUNK; ++i)
            cudaEventCreateWithFlags(&evA[i], cudaEventDisableTiming);
        cudaEvent_t e; cudaEventCreateWithFlags(&e, cudaEventDisableTiming); return e;
    }();

    static bool attrsSet = []() {
        cudaFuncSetAttribute(attn_kernel, cudaFuncAttributeMaxDynamicSharedMemorySize, A_SMEM_TOTAL);
        cudaFuncSetAttribute(edge_kernel, cudaFuncAttributeMaxDynamicSharedMemorySize, ESMEM_TOTAL);
        return true;
    }();
    (void)attrsSet;

    // prep (capture/default stream)
    wprep_kernel<<<320, 256>>>(Wq, Wv, Wn, Wk, We);
    prep2_kernel<<<128, 256>>>(qn, vn, Wk, bq, bv);

    // pipelined attn/edge overlap across two streams
    for (int c = 0; c < NCHUNK; ++c) {
        int bm0 = c * CHUNK_BM;
        attn_kernel<<<CHUNK_BM, 256, A_SMEM_TOTAL>>>(ke, bn, out, bm0);
        cudaEventRecord(evA[c], 0);
        cudaStreamWaitEvent(s2, evA[c], 0);
        edge_kernel<<<2 * CHUNK_BM, 256, ESMEM_TOTAL, s2>>>(ke, bk, be, out, bm0);
    }
    cudaEventRecord(evJoin, s2);
    cudaStreamWaitEvent(0, evJoin, 0);
}

// round 10
// speedup vs baseline: 1.2497x; 1.2497x over previous
#include <cuda_runtime.h>
#include <cuda_fp16.h>
#include <math.h>
#include <stdint.h>

// ---------------- problem constants ----------------
#define Bv 16
#define Nv 128
#define Dv 256
#define Hv 8
#define BM (Bv*Nv)                               // 2048 (b,m) pairs
#define EDGE_ELEMS ((size_t)Bv*Nv*Nv*Dv)         // 67108864
#define INV_SQRT_DK 0.17677669529663688f

// ---------------- device scratch (no runtime alloc) ----------------
__device__ float g_WqT[Dv*Dv];
__device__ float g_WvT[Dv*Dv];
__device__ float g_qW[(size_t)BM*Hv*Dv];          // [(bm*8+h)*256+j], pre-scaled
__device__ __half2 g_vprojP[(size_t)Bv*64*Dv];    // n-paired half2: [b*64+n2][d]
__device__ __half2 g_WnTp[128*Dv];                // j-paired half2: [j2][d]
// B fragments as tile-pairs: [(kt*16 + tp)*32 + lane] = (t0.b0,t0.b1,t1.b0,t1.b1)
__device__ uint4 g_fragK4[16*16*32];
__device__ uint4 g_fragE4[16*16*32];

// fast exact-identity mish: x*tanh(log1p(e^x)) == x*(u^2-1)/(u^2+1), u=1+e^x
__device__ __forceinline__ float mishf(float x) {
    if (x > 20.0f) return x;
    float t  = __expf(x);
    float u  = 1.0f + t;
    float u2 = u * u;
    return x * __fdividef(u2 - 1.0f, u2 + 1.0f);
}
__device__ __forceinline__ unsigned h2u(__half a, __half b) {
    return (unsigned)__half_as_ushort(a) | ((unsigned)__half_as_ushort(b) << 16);
}
__device__ __forceinline__ unsigned h2pack(__half2 h) {
    return *reinterpret_cast<unsigned*>(&h);
}
__device__ __forceinline__ uint32_t smem_u32(const void* p) {
    uint32_t a;
    asm("{ .reg .u64 t; cvta.to.shared.u64 t, %1; cvt.u32.u64 %0, t; }" : "=r"(a) : "l"(p));
    return a;
}
__device__ __forceinline__ void mma16816(float* d, const unsigned* a,
                                         unsigned b0, unsigned b1) {
    asm volatile(
        "mma.sync.aligned.m16n8k16.row.col.f32.f16.f16.f32 "
        "{%0,%1,%2,%3},{%4,%5,%6,%7},{%8,%9},{%0,%1,%2,%3};"
        : "+f"(d[0]), "+f"(d[1]), "+f"(d[2]), "+f"(d[3])
        : "r"(a[0]), "r"(a[1]), "r"(a[2]), "r"(a[3]), "r"(b0), "r"(b1));
}
__device__ __forceinline__ void ldsm_x4(unsigned* a, uint32_t addr) {
    asm volatile("ldmatrix.sync.aligned.m8n8.x4.shared.b16 {%0,%1,%2,%3}, [%4];"
        : "=r"(a[0]), "=r"(a[1]), "=r"(a[2]), "=r"(a[3]) : "r"(addr));
}

// ---------------- K1: weight prep (320 blocks x 256) ----------------
__global__ void wprep_kernel(const float* __restrict__ Wq, const float* __restrict__ Wv,
                             const float* __restrict__ Wn,
                             const float* __restrict__ Wk, const float* __restrict__ We) {
    int blk = blockIdx.x, tid = threadIdx.x;
    if (blk < 128) {
        int which = blk >> 6, t2 = blk & 63;
        const float* src = (which == 0) ? Wq : Wv;
        float* dst = (which == 0) ? g_WqT : g_WvT;
        __shared__ float t[32][33];
        int x0 = (t2 & 7) * 32, y0 = (t2 >> 3) * 32;
        int tx = tid & 31, ty = tid >> 5;
        #pragma unroll
        for (int i = 0; i < 32; i += 8) t[ty + i][tx] = src[(y0 + ty + i) * Dv + x0 + tx];
        __syncthreads();
        #pragma unroll
        for (int i = 0; i < 32; i += 8) dst[(x0 + ty + i) * Dv + y0 + tx] = t[tx][ty + i];
    } else if (blk < 256) {
        int e = (blk - 128) * 256 + tid;          // 0..32767
        int j2 = e >> 8, d = e & 255;
        g_WnTp[e] = __floats2half2_rn(Wn[d * Dv + 2 * j2], Wn[d * Dv + 2 * j2 + 1]);
    } else {
        int g = (blk - 256) * 256 + tid;          // 0..16383
        int mat = g >> 13;
        int r = g & 8191;
        int kt = r >> 9, tp = (r >> 5) & 15, lane = r & 31;
        const float* W = mat ? We : Wk;
        int k0 = kt * 16 + (lane & 3) * 2;
        int n0 = (2 * tp) * 8 + (lane >> 2);
        int n1 = n0 + 8;
        uint4 f;
        f.x = h2u(__float2half_rn(W[n0 * Dv + k0]),     __float2half_rn(W[n0 * Dv + k0 + 1]));
        f.y = h2u(__float2half_rn(W[n0 * Dv + k0 + 8]), __float2half_rn(W[n0 * Dv + k0 + 9]));
        f.z = h2u(__float2half_rn(W[n1 * Dv + k0]),     __float2half_rn(W[n1 * Dv + k0 + 1]));
        f.w = h2u(__float2half_rn(W[n1 * Dv + k0 + 8]), __float2half_rn(W[n1 * Dv + k0 + 9]));
        if (mat) g_fragE4[r] = f;
        else     g_fragK4[r] = f;
    }
}

// ---------------- K2: batched q/v projections + qW fold (128 CTAs x 16 bm) ----------------
__global__ void __launch_bounds__(256) prep2_kernel(
    const float* __restrict__ qn, const float* __restrict__ vn,
    const float* __restrict__ Wk,
    const float* __restrict__ bq, const float* __restrict__ bv)
{
    __shared__ float sIn[16 * 256];
    __shared__ float sQp[16 * 256];
    int tid = threadIdx.x;
    int bm0 = blockIdx.x * 16;

    for (int e = tid; e < 16 * 256; e += 256) sIn[e] = qn[(size_t)bm0 * 256 + e];
    __syncthreads();
    {
        float acc[16];
        float bqv = bq[tid];
        #pragma unroll
        for (int r = 0; r < 16; ++r) acc[r] = bqv;
        #pragma unroll 4
        for (int j = 0; j < 256; ++j) {
            float w = g_WqT[j * 256 + tid];
            #pragma unroll
            for (int r = 0; r < 16; ++r) acc[r] += sIn[r * 256 + j] * w;
        }
        #pragma unroll
        for (int r = 0; r < 16; ++r) sQp[r * 256 + tid] = acc[r];
    }
    __syncthreads();
    for (int e = tid; e < 16 * 256; e += 256) sIn[e] = vn[(size_t)bm0 * 256 + e];
    __syncthreads();
    {
        float acc[16];
        float bvv = bv[tid];
        #pragma unroll
        for (int r = 0; r < 16; ++r) acc[r] = bvv;
        #pragma unroll 4
        for (int j = 0; j < 256; ++j) {
            float w = g_WvT[j * 256 + tid];
            #pragma unroll
            for (int r = 0; r < 16; ++r) acc[r] += sIn[r * 256 + j] * w;
        }
        int b = bm0 >> 7, n2base = (bm0 & 127) >> 1;
        #pragma unroll
        for (int i = 0; i < 8; ++i)
            g_vprojP[((size_t)b * 64 + n2base + i) * 256 + tid] =
                __floats2half2_rn(acc[2 * i], acc[2 * i + 1]);
    }
    #pragma unroll 1
    for (int h = 0; h < 8; ++h) {
        float acc[16];
        #pragma unroll
        for (int r = 0; r < 16; ++r) acc[r] = 0.0f;
        #pragma unroll 4
        for (int dk = 0; dk < 32; ++dk) {
            float w = Wk[(h * 32 + dk) * 256 + tid];
            #pragma unroll
            for (int r = 0; r < 16; ++r) acc[r] += sQp[r * 256 + h * 32 + dk] * w;
        }
        #pragma unroll
        for (int r = 0; r < 16; ++r)
            g_qW[((size_t)(bm0 + r) * 8 + h) * 256 + tid] = acc[r] * INV_SQRT_DK;
    }
}

// ---------------- fused main kernel: 2048 CTAs x 512 threads, 2 CTAs/SM ----------------
#define PITCH 264
#define F_SA_OFF   0                              // 128*264*2 = 67584
#define F_QW_OFF   67584                          // 8*260*4 = 8320 -> 75904
#define F_SC_OFF   75904                          // 2*4096 score partials; [0] aliases sAttn
#define F_ND_OFF   (F_SC_OFF + 8192)              // 1024 (node partial)
#define F_BK_OFF   (F_ND_OFF + 1024)              // 1024
#define F_BE_OFF   (F_BK_OFF + 1024)              // 1024
#define F_SMEM_TOTAL (F_BE_OFF + 1024)            // 88192

// One pass over 32 rows x 32 cols x 256 k of a 128-row fp16 A in smem.
// PF: register double-buffer of B fragments.
template <bool PF>
__device__ __forceinline__ void gemm_tile(float acc[2][4][4], uint32_t lm0, uint32_t lm1,
                                          const uint4* __restrict__ frag, int tpBase) {
    #pragma unroll
    for (int mi = 0; mi < 2; ++mi)
        #pragma unroll
        for (int t = 0; t < 4; ++t)
            #pragma unroll
            for (int q = 0; q < 4; ++q) acc[mi][t][q] = 0.0f;

    const uint4* fp = frag + (size_t)tpBase * 32 + (threadIdx.x & 31);
    uint4 bf0, bf1;
    if (PF) { bf0 = __ldg(fp); bf1 = __ldg(fp + 32); }
    #pragma unroll 1
    for (int kt = 0; kt < 16; ++kt) {
        if (!PF) { bf0 = __ldg(fp + kt * 512); bf1 = __ldg(fp + kt * 512 + 32); }
        unsigned a0[4], a1[4];
        ldsm_x4(a0, lm0 + kt * 32);
        ldsm_x4(a1, lm1 + kt * 32);
        uint4 bn0, bn1;
        if (PF && kt < 15) { bn0 = __ldg(fp + (kt + 1) * 512); bn1 = __ldg(fp + (kt + 1) * 512 + 32); }
        mma16816(acc[0][0], a0, bf0.x, bf0.y);
        mma16816(acc[1][0], a1, bf0.x, bf0.y);
        mma16816(acc[0][1], a0, bf0.z, bf0.w);
        mma16816(acc[1][1], a1, bf0.z, bf0.w);
        mma16816(acc[0][2], a0, bf1.x, bf1.y);
        mma16816(acc[1][2], a1, bf1.x, bf1.y);
        mma16816(acc[0][3], a0, bf1.z, bf1.w);
        mma16816(acc[1][3], a1, bf1.z, bf1.w);
        if (PF && kt < 15) { bf0 = bn0; bf1 = bn1; }
    }
}

__global__ void __launch_bounds__(512, 2) fused_kernel(
    const float* __restrict__ key_edge,
    const float* __restrict__ bk, const float* __restrict__ be,
    const float* __restrict__ bn,
    float* __restrict__ out)
{
    extern __shared__ char sm[];
    __half* sA   = (__half*)(sm + F_SA_OFF);
    float* sQW   = (float*)(sm + F_QW_OFF);
    float* sSc   = (float*)(sm + F_SC_OFF);      // [2][8][128]; [0] is also sAttn
    float* sAttn = sSc;
    float* sNode = (float*)(sm + F_ND_OFF);
    float* sBk   = (float*)(sm + F_BK_OFF);
    float* sBe   = (float*)(sm + F_BE_OFF);

    const int tid = threadIdx.x, lane = tid & 31, warp = tid >> 5;
    const int bm = blockIdx.x, b = bm >> 7;

    if (tid < 256) { sBk[tid] = bk[tid]; sBe[tid] = be[tid]; }
    for (int i = tid; i < 8 * 256; i += 512)
        sQW[(i >> 8) * 260 + (i & 255)] = g_qW[(size_t)bm * 2048 + i];

    // ---- phase 1: KE (fp32 global) -> sA (fp16), 512 threads ----
    const float* keb = key_edge + (size_t)bm * (Nv * Dv);
    {
        const int r8 = tid >> 6, c4 = (tid & 63) * 4;
        #pragma unroll 4
        for (int rr = 0; rr < 128; rr += 8) {
            int row = rr + r8;
            float4 v = *(const float4*)&keb[(size_t)row * 256 + c4];
            uint2 p;
            p.x = h2pack(__floats2half2_rn(v.x, v.y));
            p.y = h2pack(__floats2half2_rn(v.z, v.w));
            *(uint2*)&sA[row * PITCH + c4] = p;
        }
    }
    __syncthreads();

    const int rowsel = (lane & 7) + ((lane >> 3) & 1) * 8;
    const int colsel = (lane >> 4) * 8;
    const uint32_t smbA = smem_u32(sA);

    // ---- phase 2: scores via MMA, k-split across warp pairs ----
    // warp = rw + 8*kh : rows [rw*16, rw*16+16), k-steps [kh*8, kh*8+8)
    {
        const int rw = warp & 7, kh = warp >> 3;
        uint32_t lmS = smbA + (uint32_t)(((rw * 16 + rowsel) * PITCH + colsel) * 2);
        const int hB  = lane >> 2;
        const int kq2 = (lane & 3) * 2;
        float sc[4] = {0.0f, 0.0f, 0.0f, 0.0f};
        #pragma unroll 1
        for (int ki = 0; ki < 8; ++ki) {
            int kt = kh * 8 + ki;
            unsigned a[4];
            ldsm_x4(a, lmS + kt * 32);
            float2 qa = *(float2*)&sQW[hB * 260 + kt * 16 + kq2];
            float2 qb = *(float2*)&sQW[hB * 260 + kt * 16 + kq2 + 8];
            __half2 ha = __floats2half2_rn(qa.x, qa.y);
            __half2 hb = __floats2half2_rn(qb.x, qb.y);
            float2 ra = __half22float2(ha), rb = __half22float2(hb);
            __half2 la = __floats2half2_rn(qa.x - ra.x, qa.y - ra.y);
            __half2 lb = __floats2half2_rn(qb.x - rb.x, qb.y - rb.y);
            mma16816(sc, a, h2pack(ha), h2pack(hb));   // hi
            mma16816(sc, a, h2pack(la), h2pack(lb));   // lo
        }
        int rD = rw * 16 + (lane >> 2);
        int hD = (lane & 3) * 2;
        float* dst = sSc + kh * 1024;
        dst[hD * 128 + rD]           = sc[0];
        dst[(hD + 1) * 128 + rD]     = sc[1];
        dst[hD * 128 + rD + 8]       = sc[2];
        dst[(hD + 1) * 128 + rD + 8] = sc[3];
    }
    __syncthreads();

    // ---- softmax (warps 0..7, head = warp) — sums the two k-partials ----
    if (warp < 8) {
        int h = warp;
        float s[4];
        #pragma unroll
        for (int i = 0; i < 4; ++i)
            s[i] = sSc[h * 128 + lane + 32 * i] + sSc[1024 + h * 128 + lane + 32 * i];
        float mx = fmaxf(fmaxf(s[0], s[1]), fmaxf(s[2], s[3]));
        #pragma unroll
        for (int off = 16; off > 0; off >>= 1)
            mx = fmaxf(mx, __shfl_xor_sync(0xffffffffu, mx, off));
        float e[4], sum = 0.0f;
        #pragma unroll
        for (int i = 0; i < 4; ++i) { e[i] = __expf(s[i] - mx); sum += e[i]; }
        #pragma unroll
        for (int off = 16; off > 0; off >>= 1)
            sum += __shfl_xor_sync(0xffffffffu, sum, off);
        float inv = __fdividef(1.0f, sum);
        #pragma unroll
        for (int i = 0; i < 4; ++i) sAttn[h * 128 + lane + 32 * i] = e[i] * inv;
    }
    __syncthreads();

    // ---- node path (tid<256; half2 packed) ----
    if (tid < 256) {
        int h = tid >> 5;
        const __half2* vp = g_vprojP + (size_t)b * 64 * 256 + tid;
        const float* att = &sAttn[h * 128];
        float accN = 0.0f;
        #pragma unroll 4
        for (int n2 = 0; n2 < 64; ++n2) {
            float2 v = __half22float2(vp[n2 * 256]);
            accN += att[2 * n2] * v.x + att[2 * n2 + 1] * v.y;
        }
        sNode[tid] = accN;
    }
    __syncthreads();
    if (tid < 256) {
        float acc2 = bn[tid];
        #pragma unroll 4
        for (int j2 = 0; j2 < 128; ++j2) {
            float2 w = __half22float2(g_WnTp[j2 * 256 + tid]);
            acc2 += sNode[2 * j2] * w.x + sNode[2 * j2 + 1] * w.y;
        }
        out[EDGE_ELEMS + (size_t)bm * 256 + tid] = mishf(acc2);
    }

    // ---- GEMM setup: 16 warps, tile = 32 rows x 32 cols ----
    const int wi = warp & 3;                 // m-band: rows [wi*32, wi*32+32)
    const int wj = warp >> 2;                // n-group: cols [wj*32, wj*32+32) per np
    const int rA = lane >> 2;
    const int kq = (lane & 3) * 2;
    const uint32_t lm0 = smbA + (uint32_t)(((wi * 32 + rowsel) * PITCH + colsel) * 2);
    const uint32_t lm1 = lm0 + 16 * PITCH * 2;

    float acc[2][4][4];
    unsigned pk0[2][4][2];

    // ---- GEMM1 np=0 (prefetched) ----
    gemm_tile<true>(acc, lm0, lm1, g_fragK4, 0 * 8 + wj * 2);
    #pragma unroll
    for (int mi = 0; mi < 2; ++mi) {
        #pragma unroll
        for (int t = 0; t < 4; ++t) {
            int r0 = wi * 32 + mi * 16 + rA;
            int c  = wj * 32 + t * 8 + kq;
            float b0 = sBk[c], b1 = sBk[c + 1];
            const float* attc = &sAttn[(c >> 5) * 128];
            float a0 = attc[r0], a8 = attc[r0 + 8];
            pk0[mi][t][0] = h2pack(__floats2half2_rn((acc[mi][t][0] + b0) * a0, (acc[mi][t][1] + b1) * a0));
            pk0[mi][t][1] = h2pack(__floats2half2_rn((acc[mi][t][2] + b0) * a8, (acc[mi][t][3] + b1) * a8));
        }
    }

    // ---- GEMM1 np=1 (no prefetch: pk0 live) ----
    gemm_tile<false>(acc, lm0, lm1, g_fragK4, 1 * 8 + wj * 2);
    __syncthreads();   // all ldmatrix reads of sA (KE) complete

    // write A2 = scaled k (fp16) over sA
    #pragma unroll
    for (int mi = 0; mi < 2; ++mi) {
        #pragma unroll
        for (int t = 0; t < 4; ++t) {
            int r0 = wi * 32 + mi * 16 + rA;
            int c0 = wj * 32 + t * 8 + kq;
            int c1 = 128 + c0;
            *(unsigned*)&sA[r0 * PITCH + c0]       = pk0[mi][t][0];
            *(unsigned*)&sA[(r0 + 8) * PITCH + c0] = pk0[mi][t][1];
            float b0 = sBk[c1], b1 = sBk[c1 + 1];
            const float* attc = &sAttn[(c1 >> 5) * 128];
            float a0 = attc[r0], a8 = attc[r0 + 8];
            *(unsigned*)&sA[r0 * PITCH + c1] =
                h2pack(__floats2half2_rn((acc[mi][t][0] + b0) * a0, (acc[mi][t][1] + b1) * a0));
            *(unsigned*)&sA[(r0 + 8) * PITCH + c1] =
                h2pack(__floats2half2_rn((acc[mi][t][2] + b0) * a8, (acc[mi][t][3] + b1) * a8));
        }
    }
    __syncthreads();   // A2 visible to all warps

    // ---- GEMM2: out = mish(A2 @ We^T + be) ----
    #pragma unroll 1
    for (int np = 0; np < 2; ++np) {
        gemm_tile<true>(acc, lm0, lm1, g_fragE4, np * 8 + wj * 2);
        #pragma unroll
        for (int mi = 0; mi < 2; ++mi) {
            #pragma unroll
            for (int t = 0; t < 4; ++t) {
                int r0 = wi * 32 + mi * 16 + rA;
                int c  = np * 128 + wj * 32 + t * 8 + kq;
                float b0 = sBe[c], b1 = sBe[c + 1];
                size_t gr = ((size_t)bm * 128 + r0) * 256 + c;
                float2 o0, o1;
                o0.x = mishf(acc[mi][t][0] + b0);
                o0.y = mishf(acc[mi][t][1] + b1);
                o1.x = mishf(acc[mi][t][2] + b0);
                o1.y = mishf(acc[mi][t][3] + b1);
                *(float2*)&out[gr]           = o0;
                *(float2*)&out[gr + 8 * 256] = o1;
            }
        }
    }
}

// ---------------------------------------------------------------------------
extern "C" void kernel_launch(void* const* d_in, const int* in_sizes, int n_in,
                              void* d_out, int out_size) {
    (void)in_sizes; (void)n_in; (void)out_size;
    const float* qn = (const float*)d_in[0];
    const float* vn = (const float*)d_in[1];
    const float* ke = (const float*)d_in[2];
    const float* Wq = (const float*)d_in[4];
    const float* bq = (const float*)d_in[5];
    const float* Wk = (const float*)d_in[6];
    const float* bk = (const float*)d_in[7];
    const float* Wv = (const float*)d_in[8];
    const float* bv = (const float*)d_in[9];
    const float* We = (const float*)d_in[10];
    const float* be = (const float*)d_in[11];
    const float* Wn = (const float*)d_in[12];
    const float* bn = (const float*)d_in[13];
    float* out = (float*)d_out;

    wprep_kernel<<<320, 256>>>(Wq, Wv, Wn, Wk, We);
    prep2_kernel<<<128, 256>>>(qn, vn, Wk, bq, bv);

    cudaFuncSetAttribute(fused_kernel, cudaFuncAttributeMaxDynamicSharedMemorySize, F_SMEM_TOTAL);
    fused_kernel<<<BM, 512, F_SMEM_TOTAL>>>(ke, bk, be, bn, out);
}